// round 1
// baseline (speedup 1.0000x reference)
#include <cuda_runtime.h>
#include <cstdint>

#define NN 10000
#define NE 160000
#define MS 128
#define MV 64
#define DIN 320
#define DK 64
#define NF 32
#define WN 384
#define MSGW 768   // custom layout: m0[128] | m1 i-major [3][128] | m2 i-major [3][64] | m3[64]

// Scratch (device globals — no allocation in kernel_launch)
__device__ float g_x1[NN * DIN];
__device__ float g_msg[NN * MSGW];

// ---------------------------------------------------------------------------
// K0: zero the message accumulator
// ---------------------------------------------------------------------------
__global__ void k_zero() {
    int i = blockIdx.x * blockDim.x + threadIdx.x;
    if (i < NN * MSGW / 4) ((float4*)g_msg)[i] = make_float4(0.f, 0.f, 0.f, 0.f);
}

// ---------------------------------------------------------------------------
// K1: both node linears. out = s_skip = linear(x, W_si), g_x1 = linear(x, W_l1)
// 32 nodes per block; 320 threads: tid<128 -> scalar col, else (v,i) vector.
// Register-tiles 32 node-accumulators per weight load (weights stay L1-hot).
// ---------------------------------------------------------------------------
__global__ __launch_bounds__(320) void k1(
    const float* __restrict__ x,
    const float* __restrict__ Wsis, const float* __restrict__ Wsiv,
    const float* __restrict__ Wl1s, const float* __restrict__ Wl1v,
    float* __restrict__ out)
{
    __shared__ float xs[32][DIN];   // 40 KB
    int tid  = threadIdx.x;
    int base = blockIdx.x * 32;
    int nmax = min(32, NN - base);

    for (int r = 0; r < nmax; r++)
        xs[r][tid] = x[(size_t)(base + r) * DIN + tid];
    __syncthreads();

    float aa[32], ab[32];
#pragma unroll
    for (int nd = 0; nd < 32; nd++) { aa[nd] = 0.f; ab[nd] = 0.f; }

    if (tid < MS) {
        int c = tid;
        for (int u = 0; u < MS; u++) {
            float wa = Wsis[u * MS + c];
            float wb = Wl1s[u * MS + c];
#pragma unroll
            for (int nd = 0; nd < 32; nd++) {
                float xu = xs[nd][u];
                aa[nd] = fmaf(xu, wa, aa[nd]);
                ab[nd] = fmaf(xu, wb, ab[nd]);
            }
        }
        const float sc = 0.08838834764831845f;   // 1/sqrt(128)
        for (int nd = 0; nd < nmax; nd++) {
            out [(size_t)(base + nd) * DIN + c] = aa[nd] * sc;
            g_x1[(size_t)(base + nd) * DIN + c] = ab[nd] * sc;
        }
    } else {
        int t = tid - MS, v = t / 3, i = t - 3 * v;
        for (int u = 0; u < MV; u++) {
            float wa = Wsiv[u * MV + v];
            float wb = Wl1v[u * MV + v];
#pragma unroll
            for (int nd = 0; nd < 32; nd++) {
                float xu = xs[nd][MS + 3 * u + i];
                aa[nd] = fmaf(xu, wa, aa[nd]);
                ab[nd] = fmaf(xu, wb, ab[nd]);
            }
        }
        const float sc = 0.125f;                 // 1/sqrt(64)
        int c = MS + 3 * v + i;
        for (int nd = 0; nd < nmax; nd++) {
            out [(size_t)(base + nd) * DIN + c] = aa[nd] * sc;
            g_x1[(size_t)(base + nd) * DIN + c] = ab[nd] * sc;
        }
    }
}

// ---------------------------------------------------------------------------
// K2: fused edge kernel. Persistent blocks; tp_keys (padded) + tp_weight in
// smem. One warp processes 4 edges per iteration:
//   logits (lane = filter) -> warp softmax -> w = p @ tpW (shfl-broadcast p,
//   tpW rows reused across 4 edges) -> gather x1[src] -> 768 outputs staged
//   to smem -> 6x red.global.add.v4.f32 into g_msg[dst].
// Lane l owns w indices l+32k (k=0..11) and msg cols l+32m in the i-major
// layout, so everything stays register-resident and coalesced.
// ---------------------------------------------------------------------------
__global__ __launch_bounds__(256, 2) void k2(
    const float* __restrict__ eq,  const float* __restrict__ esh,
    const float* __restrict__ keys, const float* __restrict__ tpw,
    const int* __restrict__ esrc,  const int* __restrict__ edst)
{
    extern __shared__ float sm[];
    float* ks = sm;                    // 32 x 68 (padded)   = 2176 floats
    float* tw = sm + 2176;             // 32 x 384           = 12288
    float* qb = sm + 2176 + 12288;     // 8 warps x 4 x 64   = 2048
    float* ob = qb + 2048;             // 8 warps x 768      = 6144

    int tid = threadIdx.x;
    for (int idx = tid; idx < NF * DK; idx += 256) {
        int f = idx >> 6, j = idx & 63;
        ks[f * 68 + j] = keys[idx];
    }
    for (int idx = tid; idx < NF * WN; idx += 256) tw[idx] = tpw[idx];
    __syncthreads();

    int lane = tid & 31, w = tid >> 5;
    float* qw = qb + w * 256;
    float* ow = ob + w * 768;
    const unsigned FULL = 0xffffffffu;

    for (int g = blockIdx.x; g < NE / 32; g += gridDim.x) {
        int ebase = g * 32 + w * 4;

        // stage q rows for 4 edges
#pragma unroll
        for (int e = 0; e < 4; e++) {
            float2 q2 = *(const float2*)(eq + (size_t)(ebase + e) * DK + lane * 2);
            qw[e * 64 + lane * 2]     = q2.x;
            qw[e * 64 + lane * 2 + 1] = q2.y;
        }
        __syncwarp();

        // logits: lane = filter index
        float lg[4] = {0.f, 0.f, 0.f, 0.f};
#pragma unroll
        for (int j4 = 0; j4 < 16; j4++) {
            float4 k4 = *(const float4*)&ks[lane * 68 + j4 * 4];
#pragma unroll
            for (int e = 0; e < 4; e++) {
                float4 q4 = *(const float4*)&qw[e * 64 + j4 * 4];
                lg[e] = fmaf(k4.x, q4.x, fmaf(k4.y, q4.y,
                         fmaf(k4.z, q4.z, fmaf(k4.w, q4.w, lg[e]))));
            }
        }

        // softmax over the 32 filters (warp reductions)
        float p[4];
#pragma unroll
        for (int e = 0; e < 4; e++) {
            float l = lg[e] * 0.125f;          // 1/sqrt(64)
            float m = l;
#pragma unroll
            for (int o = 16; o > 0; o >>= 1) m = fmaxf(m, __shfl_xor_sync(FULL, m, o));
            float ex = __expf(l - m);
            float s = ex;
#pragma unroll
            for (int o = 16; o > 0; o >>= 1) s += __shfl_xor_sync(FULL, s, o);
            p[e] = ex / s;
        }

        // w = p @ tp_weight ; lane owns w cols lane+32k, k=0..11
        float wa[4][12];
#pragma unroll
        for (int k = 0; k < 12; k++) { wa[0][k]=0.f; wa[1][k]=0.f; wa[2][k]=0.f; wa[3][k]=0.f; }
        for (int f = 0; f < NF; f++) {
            float pf0 = __shfl_sync(FULL, p[0], f);
            float pf1 = __shfl_sync(FULL, p[1], f);
            float pf2 = __shfl_sync(FULL, p[2], f);
            float pf3 = __shfl_sync(FULL, p[3], f);
            const float* t = tw + f * WN + lane;
#pragma unroll
            for (int k = 0; k < 12; k++) {
                float tv = t[32 * k];
                wa[0][k] = fmaf(pf0, tv, wa[0][k]);
                wa[1][k] = fmaf(pf1, tv, wa[1][k]);
                wa[2][k] = fmaf(pf2, tv, wa[2][k]);
                wa[3][k] = fmaf(pf3, tv, wa[3][k]);
            }
        }

        // per-edge: gather x1[src], build 768 outputs, vector-red into g_msg
#pragma unroll
        for (int e = 0; e < 4; e++) {
            int row = ebase + e;
            int src = esrc[row];
            int dst = edst[row];
            float4 sh = *(const float4*)(esh + (size_t)row * 4);
            const float* xg = g_x1 + (size_t)src * DIN;

            float xsv[4];
#pragma unroll
            for (int m = 0; m < 4; m++) xsv[m] = xg[lane + 32 * m];

            float xv[2][3];
#pragma unroll
            for (int k2 = 0; k2 < 2; k2++) {
                int u = lane + 32 * k2;
                const float* pv = xg + MS + 3 * u;
                xv[k2][0] = pv[0]; xv[k2][1] = pv[1]; xv[k2][2] = pv[2];
            }

            // o0: w0[j]*xs[j]*sh0
#pragma unroll
            for (int m = 0; m < 4; m++)
                ow[lane + 32 * m] = wa[e][m] * xsv[m] * sh.x;
            // o1 (i-major): w1[j]*xs[j]*sh1[i]
#pragma unroll
            for (int m = 0; m < 4; m++) {
                float tt = wa[e][4 + m] * xsv[m];
                ow[128 + 0 * 128 + lane + 32 * m] = tt * sh.y;
                ow[128 + 1 * 128 + lane + 32 * m] = tt * sh.z;
                ow[128 + 2 * 128 + lane + 32 * m] = tt * sh.w;
            }
            // o2 (i-major) + o3
#pragma unroll
            for (int k2 = 0; k2 < 2; k2++) {
                int u = lane + 32 * k2;
                float s2 = wa[e][8 + k2] * sh.x;
                ow[512 + 0 * 64 + u] = s2 * xv[k2][0];
                ow[512 + 1 * 64 + u] = s2 * xv[k2][1];
                ow[512 + 2 * 64 + u] = s2 * xv[k2][2];
                float d = xv[k2][0] * sh.y + xv[k2][1] * sh.z + xv[k2][2] * sh.w;
                ow[704 + u] = wa[e][10 + k2] * d * 0.5773502691896258f;  // 1/sqrt(3)
            }
            __syncwarp();

            float* mrow = g_msg + (size_t)dst * MSGW;
#pragma unroll
            for (int m6 = 0; m6 < 6; m6++) {
                float4 v4 = *(const float4*)&ow[m6 * 128 + lane * 4];
                asm volatile("red.global.add.v4.f32 [%0], {%1,%2,%3,%4};"
                             :: "l"(mrow + m6 * 128 + lane * 4),
                                "f"(v4.x), "f"(v4.y), "f"(v4.z), "f"(v4.w)
                             : "memory");
            }
            __syncwarp();
        }
    }
}

// ---------------------------------------------------------------------------
// K3: output linear from g_msg (custom layout) + add into out (=s_skip).
// 16 nodes per block, 320 threads, same thread mapping as K1.
// ---------------------------------------------------------------------------
__global__ __launch_bounds__(320) void k3(
    const float* __restrict__ W2s0, const float* __restrict__ W2s3,
    const float* __restrict__ W2v1, const float* __restrict__ W2v2,
    float* __restrict__ out)
{
    __shared__ float ms[16][MSGW];   // 48 KB
    int tid  = threadIdx.x;
    int base = blockIdx.x * 16;

    for (int idx = tid; idx < 16 * MSGW; idx += 320) {
        int r = idx / MSGW, c = idx - r * MSGW;
        ms[r][c] = g_msg[(size_t)(base + r) * MSGW + c];
    }
    __syncthreads();

    float acc[16];
#pragma unroll
    for (int nd = 0; nd < 16; nd++) acc[nd] = 0.f;

    const float sc = 0.07216878364870323f * 0.1f;   // 1/sqrt(192) * 1/10

    if (tid < MS) {
        int c = tid;
        for (int u = 0; u < MS; u++) {
            float wv = W2s0[u * MS + c];
#pragma unroll
            for (int nd = 0; nd < 16; nd++) acc[nd] = fmaf(ms[nd][u], wv, acc[nd]);
        }
        for (int u = 0; u < MV; u++) {
            float wv = W2s3[u * MS + c];
#pragma unroll
            for (int nd = 0; nd < 16; nd++) acc[nd] = fmaf(ms[nd][704 + u], wv, acc[nd]);
        }
        for (int nd = 0; nd < 16; nd++)
            out[(size_t)(base + nd) * DIN + c] += acc[nd] * sc;
    } else {
        int t = tid - MS, v = t / 3, i = t - 3 * v;
        for (int u = 0; u < MS; u++) {
            float wv = W2v1[u * MV + v];
#pragma unroll
            for (int nd = 0; nd < 16; nd++) acc[nd] = fmaf(ms[nd][128 + i * 128 + u], wv, acc[nd]);
        }
        for (int u = 0; u < MV; u++) {
            float wv = W2v2[u * MV + v];
#pragma unroll
            for (int nd = 0; nd < 16; nd++) acc[nd] = fmaf(ms[nd][512 + i * 64 + u], wv, acc[nd]);
        }
        int c = MS + 3 * v + i;
        for (int nd = 0; nd < 16; nd++)
            out[(size_t)(base + nd) * DIN + c] += acc[nd] * sc;
    }
}

// ---------------------------------------------------------------------------
extern "C" void kernel_launch(void* const* d_in, const int* in_sizes, int n_in,
                              void* d_out, int out_size)
{
    const float* x    = (const float*)d_in[0];
    const float* eq   = (const float*)d_in[1];
    const float* esh  = (const float*)d_in[2];
    const float* Wsis = (const float*)d_in[3];
    const float* Wsiv = (const float*)d_in[4];
    const float* Wl1s = (const float*)d_in[5];
    const float* Wl1v = (const float*)d_in[6];
    const float* keys = (const float*)d_in[7];
    const float* tpw  = (const float*)d_in[8];
    const float* W2s0 = (const float*)d_in[9];
    const float* W2s3 = (const float*)d_in[10];
    const float* W2v1 = (const float*)d_in[11];
    const float* W2v2 = (const float*)d_in[12];
    const int*   esrc = (const int*)d_in[13];
    const int*   edst = (const int*)d_in[14];
    float* out = (float*)d_out;

    const int smem_k2 = 22656 * 4;   // 90624 B dynamic smem
    cudaFuncSetAttribute(k2, cudaFuncAttributeMaxDynamicSharedMemorySize, smem_k2);

    k_zero<<<7500, 256>>>();
    k1<<<313, 320>>>(x, Wsis, Wsiv, Wl1s, Wl1v, out);
    k2<<<444, 256, smem_k2>>>(eq, esh, keys, tpw, esrc, edst);
    k3<<<625, 320>>>(W2s0, W2s3, W2v1, W2v2, out);
}

// round 2
// speedup vs baseline: 1.3693x; 1.3693x over previous
#include <cuda_runtime.h>
#include <cstdint>

#define NN 10000
#define NE 160000
#define MS 128
#define MV 64
#define DIN 320
#define DK 64
#define NF 32
#define WN 384
#define MSGW 768   // custom layout: m0[128] | m1 i-major [3][128] | m2 i-major [3][64] | m3[64]

// Scratch (device globals — no allocation in kernel_launch)
__device__ float g_x1[NN * DIN];
__device__ float g_msg[NN * MSGW];

// ---------------------------------------------------------------------------
// K0: zero the message accumulator
// ---------------------------------------------------------------------------
__global__ void k_zero() {
    int i = blockIdx.x * blockDim.x + threadIdx.x;
    if (i < NN * MSGW / 4) ((float4*)g_msg)[i] = make_float4(0.f, 0.f, 0.f, 0.f);
}

// ---------------------------------------------------------------------------
// K1: both node linears, smem-tiled GEMM style.
// 16 nodes/block, 256 threads, ~103KB dynamic smem (2 blocks/SM).
// Two passes over the staged x tile: pass0 -> out (s_skip, W_si),
// pass1 -> g_x1 (W_l1). Weights fully staged in smem per pass.
// Scalar: 32 colthreads x 8 nodethreads, each 2 nodes x 4 cols (8 acc).
// Vector: 16 vthreads x 16 nodethreads, each 1 node x 3 i x 4 v (12 acc).
// ---------------------------------------------------------------------------
#define K1_XP 324   // padded x-row stride in smem
__global__ __launch_bounds__(256, 2) void k1(
    const float* __restrict__ x,
    const float* __restrict__ Wsis, const float* __restrict__ Wsiv,
    const float* __restrict__ Wl1s, const float* __restrict__ Wl1v,
    float* __restrict__ out)
{
    extern __shared__ float sm[];
    float* xs = sm;                 // 16 x 324 = 5184
    float* ws = sm + 16 * K1_XP;    // 128 x 128 = 16384
    float* wv = ws + MS * MS;       // 64 x 64   = 4096

    int tid  = threadIdx.x;
    int base = blockIdx.x * 16;

    // stage x tile (float4)
    for (int idx = tid; idx < 16 * 80; idx += 256) {
        int r = idx / 80, c4 = idx - r * 80;
        float4 v = ((const float4*)(x + (size_t)(base + r) * DIN))[c4];
        *(float4*)&xs[r * K1_XP + c4 * 4] = v;
    }

    const int ct = tid & 31, nt = tid >> 5;     // scalar map
    const int c0 = ct * 4,  n0 = nt * 2;
    const int vt = tid & 15, rt = tid >> 4;     // vector map
    const int v0 = vt * 4;

#pragma unroll 1
    for (int pass = 0; pass < 2; pass++) {
        const float* Ws = pass ? Wl1s : Wsis;
        const float* Wv = pass ? Wl1v : Wsiv;
        float* dst = pass ? g_x1 : out;

        __syncthreads();   // previous-pass readers done before restaging
        for (int idx = tid; idx < MS * MS / 4; idx += 256)
            ((float4*)ws)[idx] = ((const float4*)Ws)[idx];
        for (int idx = tid; idx < MV * MV / 4; idx += 256)
            ((float4*)wv)[idx] = ((const float4*)Wv)[idx];
        __syncthreads();

        // ---- scalar part: C[16n x 128c] = xs[:, :128] @ Ws / sqrt(128)
        {
            float acc[2][4];
#pragma unroll
            for (int j = 0; j < 2; j++)
#pragma unroll
                for (int q = 0; q < 4; q++) acc[j][q] = 0.f;

#pragma unroll 4
            for (int k = 0; k < MS; k++) {
                float4 w = *(const float4*)&ws[k * MS + c0];
                float a0 = xs[n0 * K1_XP + k];
                float a1 = xs[(n0 + 1) * K1_XP + k];
                acc[0][0] = fmaf(a0, w.x, acc[0][0]);
                acc[0][1] = fmaf(a0, w.y, acc[0][1]);
                acc[0][2] = fmaf(a0, w.z, acc[0][2]);
                acc[0][3] = fmaf(a0, w.w, acc[0][3]);
                acc[1][0] = fmaf(a1, w.x, acc[1][0]);
                acc[1][1] = fmaf(a1, w.y, acc[1][1]);
                acc[1][2] = fmaf(a1, w.z, acc[1][2]);
                acc[1][3] = fmaf(a1, w.w, acc[1][3]);
            }
            const float sc = 0.08838834764831845f;   // 1/sqrt(128)
#pragma unroll
            for (int j = 0; j < 2; j++) {
                float4 o;
                o.x = acc[j][0] * sc; o.y = acc[j][1] * sc;
                o.z = acc[j][2] * sc; o.w = acc[j][3] * sc;
                *(float4*)&dst[(size_t)(base + n0 + j) * DIN + c0] = o;
            }
        }

        // ---- vector part: C[n, v, i] = sum_u xs[n][128+3u+i] * Wv[u][v] / 8
        {
            float acc[3][4];
#pragma unroll
            for (int i = 0; i < 3; i++)
#pragma unroll
                for (int q = 0; q < 4; q++) acc[i][q] = 0.f;

#pragma unroll 4
            for (int u = 0; u < MV; u++) {
                float4 w = *(const float4*)&wv[u * MV + v0];
                float a0 = xs[rt * K1_XP + MS + 3 * u];
                float a1 = xs[rt * K1_XP + MS + 3 * u + 1];
                float a2 = xs[rt * K1_XP + MS + 3 * u + 2];
                acc[0][0] = fmaf(a0, w.x, acc[0][0]);
                acc[0][1] = fmaf(a0, w.y, acc[0][1]);
                acc[0][2] = fmaf(a0, w.z, acc[0][2]);
                acc[0][3] = fmaf(a0, w.w, acc[0][3]);
                acc[1][0] = fmaf(a1, w.x, acc[1][0]);
                acc[1][1] = fmaf(a1, w.y, acc[1][1]);
                acc[1][2] = fmaf(a1, w.z, acc[1][2]);
                acc[1][3] = fmaf(a1, w.w, acc[1][3]);
                acc[2][0] = fmaf(a2, w.x, acc[2][0]);
                acc[2][1] = fmaf(a2, w.y, acc[2][1]);
                acc[2][2] = fmaf(a2, w.z, acc[2][2]);
                acc[2][3] = fmaf(a2, w.w, acc[2][3]);
            }
            const float sc = 0.125f;                 // 1/sqrt(64)
            float* drow = dst + (size_t)(base + rt) * DIN + MS;
#pragma unroll
            for (int i = 0; i < 3; i++)
#pragma unroll
                for (int q = 0; q < 4; q++)
                    drow[3 * (v0 + q) + i] = acc[i][q] * sc;
        }
    }
}

// ---------------------------------------------------------------------------
// K2: fused edge kernel (unchanged logic). Persistent blocks; tp_keys +
// tp_weight in smem. One warp processes 4 edges per iteration: logits ->
// warp softmax -> w = p @ tpW -> gather x1[src] -> 768 outputs staged to
// smem -> 6x red.global.add.v4.f32 into g_msg[dst].
// ---------------------------------------------------------------------------
__global__ __launch_bounds__(256, 2) void k2(
    const float* __restrict__ eq,  const float* __restrict__ esh,
    const float* __restrict__ keys, const float* __restrict__ tpw,
    const int* __restrict__ esrc,  const int* __restrict__ edst)
{
    extern __shared__ float sm[];
    float* ks = sm;                    // 32 x 68 (padded)   = 2176 floats
    float* tw = sm + 2176;             // 32 x 384           = 12288
    float* qb = sm + 2176 + 12288;     // 8 warps x 4 x 64   = 2048
    float* ob = qb + 2048;             // 8 warps x 768      = 6144

    int tid = threadIdx.x;
    for (int idx = tid; idx < NF * DK; idx += 256) {
        int f = idx >> 6, j = idx & 63;
        ks[f * 68 + j] = keys[idx];
    }
    for (int idx = tid; idx < NF * WN; idx += 256) tw[idx] = tpw[idx];
    __syncthreads();

    int lane = tid & 31, w = tid >> 5;
    float* qw = qb + w * 256;
    float* ow = ob + w * 768;
    const unsigned FULL = 0xffffffffu;

    for (int g = blockIdx.x; g < NE / 32; g += gridDim.x) {
        int ebase = g * 32 + w * 4;

#pragma unroll
        for (int e = 0; e < 4; e++) {
            float2 q2 = *(const float2*)(eq + (size_t)(ebase + e) * DK + lane * 2);
            qw[e * 64 + lane * 2]     = q2.x;
            qw[e * 64 + lane * 2 + 1] = q2.y;
        }
        __syncwarp();

        float lg[4] = {0.f, 0.f, 0.f, 0.f};
#pragma unroll
        for (int j4 = 0; j4 < 16; j4++) {
            float4 k4 = *(const float4*)&ks[lane * 68 + j4 * 4];
#pragma unroll
            for (int e = 0; e < 4; e++) {
                float4 q4 = *(const float4*)&qw[e * 64 + j4 * 4];
                lg[e] = fmaf(k4.x, q4.x, fmaf(k4.y, q4.y,
                         fmaf(k4.z, q4.z, fmaf(k4.w, q4.w, lg[e]))));
            }
        }

        float p[4];
#pragma unroll
        for (int e = 0; e < 4; e++) {
            float l = lg[e] * 0.125f;
            float m = l;
#pragma unroll
            for (int o = 16; o > 0; o >>= 1) m = fmaxf(m, __shfl_xor_sync(FULL, m, o));
            float ex = __expf(l - m);
            float s = ex;
#pragma unroll
            for (int o = 16; o > 0; o >>= 1) s += __shfl_xor_sync(FULL, s, o);
            p[e] = ex / s;
        }

        float wa[4][12];
#pragma unroll
        for (int k = 0; k < 12; k++) { wa[0][k]=0.f; wa[1][k]=0.f; wa[2][k]=0.f; wa[3][k]=0.f; }
        for (int f = 0; f < NF; f++) {
            float pf0 = __shfl_sync(FULL, p[0], f);
            float pf1 = __shfl_sync(FULL, p[1], f);
            float pf2 = __shfl_sync(FULL, p[2], f);
            float pf3 = __shfl_sync(FULL, p[3], f);
            const float* t = tw + f * WN + lane;
#pragma unroll
            for (int k = 0; k < 12; k++) {
                float tv = t[32 * k];
                wa[0][k] = fmaf(pf0, tv, wa[0][k]);
                wa[1][k] = fmaf(pf1, tv, wa[1][k]);
                wa[2][k] = fmaf(pf2, tv, wa[2][k]);
                wa[3][k] = fmaf(pf3, tv, wa[3][k]);
            }
        }

#pragma unroll
        for (int e = 0; e < 4; e++) {
            int row = ebase + e;
            int src = esrc[row];
            int dst = edst[row];
            float4 sh = *(const float4*)(esh + (size_t)row * 4);
            const float* xg = g_x1 + (size_t)src * DIN;

            float xsv[4];
#pragma unroll
            for (int m = 0; m < 4; m++) xsv[m] = xg[lane + 32 * m];

            float xv[2][3];
#pragma unroll
            for (int k2i = 0; k2i < 2; k2i++) {
                int u = lane + 32 * k2i;
                const float* pv = xg + MS + 3 * u;
                xv[k2i][0] = pv[0]; xv[k2i][1] = pv[1]; xv[k2i][2] = pv[2];
            }

#pragma unroll
            for (int m = 0; m < 4; m++)
                ow[lane + 32 * m] = wa[e][m] * xsv[m] * sh.x;
#pragma unroll
            for (int m = 0; m < 4; m++) {
                float tt = wa[e][4 + m] * xsv[m];
                ow[128 + 0 * 128 + lane + 32 * m] = tt * sh.y;
                ow[128 + 1 * 128 + lane + 32 * m] = tt * sh.z;
                ow[128 + 2 * 128 + lane + 32 * m] = tt * sh.w;
            }
#pragma unroll
            for (int k2i = 0; k2i < 2; k2i++) {
                int u = lane + 32 * k2i;
                float s2 = wa[e][8 + k2i] * sh.x;
                ow[512 + 0 * 64 + u] = s2 * xv[k2i][0];
                ow[512 + 1 * 64 + u] = s2 * xv[k2i][1];
                ow[512 + 2 * 64 + u] = s2 * xv[k2i][2];
                float d = xv[k2i][0] * sh.y + xv[k2i][1] * sh.z + xv[k2i][2] * sh.w;
                ow[704 + u] = wa[e][10 + k2i] * d * 0.5773502691896258f;
            }
            __syncwarp();

            float* mrow = g_msg + (size_t)dst * MSGW;
#pragma unroll
            for (int m6 = 0; m6 < 6; m6++) {
                float4 v4 = *(const float4*)&ow[m6 * 128 + lane * 4];
                asm volatile("red.global.add.v4.f32 [%0], {%1,%2,%3,%4};"
                             :: "l"(mrow + m6 * 128 + lane * 4),
                                "f"(v4.x), "f"(v4.y), "f"(v4.z), "f"(v4.w)
                             : "memory");
            }
            __syncwarp();
        }
    }
}

// ---------------------------------------------------------------------------
// K3: output linear, smem-tiled GEMM style. 32 nodes/block, 256 threads,
// ~197KB dynamic smem (1 block/SM). msg tile fully staged; weights staged
// per pass. Pass1 scalar: 4n x 4c (16 acc), K=192 = [m0;m3].
// Pass2 vector: 2n x 3i x 4v (24 acc), K=192 = [m1_i;m2_i], weights shared
// across i.
// ---------------------------------------------------------------------------
#define K3_MP 772   // padded msg-row stride in smem
__global__ __launch_bounds__(256, 1) void k3(
    const float* __restrict__ W2s0, const float* __restrict__ W2s3,
    const float* __restrict__ W2v1, const float* __restrict__ W2v2,
    float* __restrict__ out)
{
    extern __shared__ float sm[];
    float* ms = sm;                 // 32 x 772 = 24704
    float* ws = sm + 32 * K3_MP;    // up to 192 x 128 = 24576

    int tid  = threadIdx.x;
    int base = blockIdx.x * 32;
    int nmax = min(32, NN - base);

    // stage msg tile (float4), zero-pad invalid rows
    for (int idx = tid; idx < 32 * 192; idx += 256) {
        int r = idx / 192, c4 = idx - r * 192;
        float4 v = make_float4(0.f, 0.f, 0.f, 0.f);
        if (r < nmax)
            v = ((const float4*)(g_msg + (size_t)(base + r) * MSGW))[c4];
        *(float4*)&ms[r * K3_MP + c4 * 4] = v;
    }
    // stage scalar weights: ws rows 0..127 = W2s0, 128..191 = W2s3
    for (int idx = tid; idx < MS * MS / 4; idx += 256)
        ((float4*)ws)[idx] = ((const float4*)W2s0)[idx];
    for (int idx = tid; idx < MV * MS / 4; idx += 256)
        ((float4*)(ws + MS * MS))[idx] = ((const float4*)W2s3)[idx];
    __syncthreads();

    const float sc = 0.007216878364870323f;   // 1/sqrt(192) / 10

    // ---- pass 1: scalar cols
    {
        const int ct = tid & 31, nt = tid >> 5;
        const int c0 = ct * 4,  n0 = nt * 4;
        float acc[4][4];
#pragma unroll
        for (int j = 0; j < 4; j++)
#pragma unroll
            for (int q = 0; q < 4; q++) acc[j][q] = 0.f;

#pragma unroll 4
        for (int k = 0; k < MS; k++) {
            float4 w = *(const float4*)&ws[k * MS + c0];
#pragma unroll
            for (int j = 0; j < 4; j++) {
                float a = ms[(n0 + j) * K3_MP + k];
                acc[j][0] = fmaf(a, w.x, acc[j][0]);
                acc[j][1] = fmaf(a, w.y, acc[j][1]);
                acc[j][2] = fmaf(a, w.z, acc[j][2]);
                acc[j][3] = fmaf(a, w.w, acc[j][3]);
            }
        }
#pragma unroll 4
        for (int k = 0; k < MV; k++) {
            float4 w = *(const float4*)&ws[(MS + k) * MS + c0];
#pragma unroll
            for (int j = 0; j < 4; j++) {
                float a = ms[(n0 + j) * K3_MP + 704 + k];
                acc[j][0] = fmaf(a, w.x, acc[j][0]);
                acc[j][1] = fmaf(a, w.y, acc[j][1]);
                acc[j][2] = fmaf(a, w.z, acc[j][2]);
                acc[j][3] = fmaf(a, w.w, acc[j][3]);
            }
        }
#pragma unroll
        for (int j = 0; j < 4; j++) {
            if (n0 + j < nmax) {
                float4* p = (float4*)&out[(size_t)(base + n0 + j) * DIN + c0];
                float4 o = *p;
                o.x += acc[j][0] * sc; o.y += acc[j][1] * sc;
                o.z += acc[j][2] * sc; o.w += acc[j][3] * sc;
                *p = o;
            }
        }
    }

    // ---- pass 2: vector cols
    __syncthreads();
    for (int idx = tid; idx < MS * MV / 4; idx += 256)
        ((float4*)ws)[idx] = ((const float4*)W2v1)[idx];
    for (int idx = tid; idx < MV * MV / 4; idx += 256)
        ((float4*)(ws + MS * MV))[idx] = ((const float4*)W2v2)[idx];
    __syncthreads();

    {
        const int vt = tid & 15, rt = tid >> 4;
        const int v0 = vt * 4;
        float acc[2][3][4];
#pragma unroll
        for (int jn = 0; jn < 2; jn++)
#pragma unroll
            for (int i = 0; i < 3; i++)
#pragma unroll
                for (int q = 0; q < 4; q++) acc[jn][i][q] = 0.f;

#pragma unroll 2
        for (int k = 0; k < MS; k++) {
            float4 w = *(const float4*)&ws[k * MV + v0];
#pragma unroll
            for (int jn = 0; jn < 2; jn++)
#pragma unroll
                for (int i = 0; i < 3; i++) {
                    float a = ms[(rt * 2 + jn) * K3_MP + MS + 128 * i + k];
                    acc[jn][i][0] = fmaf(a, w.x, acc[jn][i][0]);
                    acc[jn][i][1] = fmaf(a, w.y, acc[jn][i][1]);
                    acc[jn][i][2] = fmaf(a, w.z, acc[jn][i][2]);
                    acc[jn][i][3] = fmaf(a, w.w, acc[jn][i][3]);
                }
        }
#pragma unroll 2
        for (int k = 0; k < MV; k++) {
            float4 w = *(const float4*)&ws[MS * MV + k * MV + v0];
#pragma unroll
            for (int jn = 0; jn < 2; jn++)
#pragma unroll
                for (int i = 0; i < 3; i++) {
                    float a = ms[(rt * 2 + jn) * K3_MP + 512 + 64 * i + k];
                    acc[jn][i][0] = fmaf(a, w.x, acc[jn][i][0]);
                    acc[jn][i][1] = fmaf(a, w.y, acc[jn][i][1]);
                    acc[jn][i][2] = fmaf(a, w.z, acc[jn][i][2]);
                    acc[jn][i][3] = fmaf(a, w.w, acc[jn][i][3]);
                }
        }
#pragma unroll
        for (int jn = 0; jn < 2; jn++) {
            int n = rt * 2 + jn;
            if (n < nmax) {
                float* drow = out + (size_t)(base + n) * DIN + MS;
#pragma unroll
                for (int i = 0; i < 3; i++)
#pragma unroll
                    for (int q = 0; q < 4; q++)
                        drow[3 * (v0 + q) + i] += acc[jn][i][q] * sc;
            }
        }
    }
}

// ---------------------------------------------------------------------------
extern "C" void kernel_launch(void* const* d_in, const int* in_sizes, int n_in,
                              void* d_out, int out_size)
{
    const float* x    = (const float*)d_in[0];
    const float* eq   = (const float*)d_in[1];
    const float* esh  = (const float*)d_in[2];
    const float* Wsis = (const float*)d_in[3];
    const float* Wsiv = (const float*)d_in[4];
    const float* Wl1s = (const float*)d_in[5];
    const float* Wl1v = (const float*)d_in[6];
    const float* keys = (const float*)d_in[7];
    const float* tpw  = (const float*)d_in[8];
    const float* W2s0 = (const float*)d_in[9];
    const float* W2s3 = (const float*)d_in[10];
    const float* W2v1 = (const float*)d_in[11];
    const float* W2v2 = (const float*)d_in[12];
    const int*   esrc = (const int*)d_in[13];
    const int*   edst = (const int*)d_in[14];
    float* out = (float*)d_out;

    const int smem_k1 = (16 * K1_XP + MS * MS + MV * MV) * 4;           // ~102.7 KB
    const int smem_k2 = 22656 * 4;                                      // ~90.6 KB
    const int smem_k3 = (32 * K3_MP + 192 * MS) * 4;                    // ~197.1 KB
    static bool attr_done = false;
    if (!attr_done) {
        cudaFuncSetAttribute(k1, cudaFuncAttributeMaxDynamicSharedMemorySize, smem_k1);
        cudaFuncSetAttribute(k2, cudaFuncAttributeMaxDynamicSharedMemorySize, smem_k2);
        cudaFuncSetAttribute(k3, cudaFuncAttributeMaxDynamicSharedMemorySize, smem_k3);
        attr_done = true;
    }

    k_zero<<<7500, 256>>>();
    k1<<<625, 256, smem_k1>>>(x, Wsis, Wsiv, Wl1s, Wl1v, out);
    k2<<<296, 256, smem_k2>>>(eq, esh, keys, tpw, esrc, edst);
    k3<<<313, 256, smem_k3>>>(W2s0, W2s3, W2v1, W2v2, out);
}